// round 1
// baseline (speedup 1.0000x reference)
#include <cuda_runtime.h>

#define NC 16
#define EPSV 1e-6f
#define B_DIM 2
#define D_DIM 8
#define H_DIM 96
#define W_DIM 96
#define DHW (D_DIM*H_DIM*W_DIM)     // 73728
#define HW  (H_DIM*W_DIM)           // 9216

#define TH 8
#define TW 32
#define NTHREADS (TH*TW)            // 256
#define HALO_H (TH+2)               // 10
#define HALO_W (TW+2)               // 34
#define SH_PLANE (HALO_H*HALO_W)    // 340
#define SH_ELEMS (3*NC*SH_PLANE)    // 16320 floats
#define SV_ELEMS (27*NTHREADS)      // 6912 floats
#define TAILW_OFF (SH_ELEMS + SV_ELEMS)
#define SMEM_FLOATS (TAILW_OFF + 256)
#define SMEM_BYTES (SMEM_FLOATS * 4)

// 9.4 MB scratch for head output h[b][c][d][y][x]
__device__ float g_h[(size_t)B_DIM * NC * DHW];

// ---------------------------------------------------------------------------
// Kernel 1: h = relu(head_w @ x), per spatial location all 16 channels.
// ---------------------------------------------------------------------------
__global__ void head_kernel(const float* __restrict__ x,
                            const float* __restrict__ head_w) {
    __shared__ float sw[NC * NC];
    if (threadIdx.x < NC * NC) sw[threadIdx.x] = head_w[threadIdx.x];
    __syncthreads();

    int idx = blockIdx.x * blockDim.x + threadIdx.x;   // over b*D*H*W
    if (idx >= B_DIM * DHW) return;
    int b = idx / DHW;
    int s = idx - b * DHW;

    const float* xb = x + (size_t)b * NC * DHW + s;
    float xv[NC];
#pragma unroll
    for (int c = 0; c < NC; c++) xv[c] = xb[(size_t)c * DHW];

    float* hb = g_h + (size_t)b * NC * DHW + s;
#pragma unroll
    for (int o = 0; o < NC; o++) {
        float a = 0.f;
#pragma unroll
        for (int c = 0; c < NC; c++) a = fmaf(sw[o * NC + c], xv[c], a);
        hb[(size_t)o * DHW] = fmaxf(a, 0.f);
    }
}

// ---------------------------------------------------------------------------
// Kernel 2: per-location rank-degenerate NMF + tail.
//   X[c,k] = h[c, clamp(d+kt-1), clamp(y+ki-1), clamp(x+kj-1)],
//   k = (ki*3+kj)*3+kt, center = 13.
// ---------------------------------------------------------------------------
__global__ void __launch_bounds__(NTHREADS)
nmf_kernel(const float* __restrict__ tail_w, float* __restrict__ out) {
    extern __shared__ float smem[];
    float* sh = smem;                 // [3][16][10][34] h halo tile
    float* sv = smem + SH_ELEMS;      // [27][256] per-thread v
    float* st = smem + TAILW_OFF;     // [256] tail weights

    const int tid = threadIdx.x;
    const int bz = blockIdx.z;
    const int b  = bz >> 3;
    const int d  = bz & 7;
    const int y0 = blockIdx.y * TH;
    const int x0 = blockIdx.x * TW;

    if (tid < NC * NC) st[tid] = tail_w[tid];

    // Stage h halo tile (replicate-clamped) into shared.
    for (int i = tid; i < SH_ELEMS; i += NTHREADS) {
        int xx = i % HALO_W;
        int r  = i / HALO_W;
        int yy = r % HALO_H;
        r /= HALO_H;
        int c  = r % NC;
        int kt = r / NC;
        int gd = min(max(d + kt - 1, 0), D_DIM - 1);
        int gy = min(max(y0 + yy - 1, 0), H_DIM - 1);
        int gx = min(max(x0 + xx - 1, 0), W_DIM - 1);
        sh[i] = g_h[(((size_t)(b * NC + c) * D_DIM + gd) * H_DIM + gy) * W_DIM + gx];
    }
    __syncthreads();

    const int ty = tid >> 5;
    const int tx = tid & 31;
    // X(c, kt, ki, kj) = shp[kt*NC*SH_PLANE + c*SH_PLANE + ki*HALO_W + kj]
    const float* shp = sh + ty * HALO_W + tx;

    float u[NC];
#pragma unroll
    for (int c = 0; c < NC; c++) u[c] = 0.f;

    // ---- init pass: u[c] = mean_k X, v[k] = mean_c X ----
#pragma unroll 1
    for (int kk = 0; kk < 9; kk++) {          // kk = ki*3+kj
        int ki = kk / 3, kj = kk - 3 * ki;
        const float* pbase = shp + ki * HALO_W + kj;
#pragma unroll
        for (int kt = 0; kt < 3; kt++) {
            const float* p = pbase + kt * (NC * SH_PLANE);
            float s = 0.f;
#pragma unroll
            for (int c = 0; c < NC; c++) {
                float xv = p[c * SH_PLANE];
                s += xv;
                u[c] += xv;
            }
            sv[(kk * 3 + kt) * NTHREADS + tid] = s * (1.f / 16.f);
        }
    }
#pragma unroll
    for (int c = 0; c < NC; c++) u[c] *= (1.f / 27.f);

    // ---- 3 NMF steps ----
#pragma unroll 1
    for (int step = 0; step < 3; step++) {
        float uu = 0.f;
#pragma unroll
        for (int c = 0; c < NC; c++) uu = fmaf(u[c], u[c], uu);
        const float t_uu = 3.f * uu;

        float nu[NC];
#pragma unroll
        for (int c = 0; c < NC; c++) nu[c] = 0.f;
        float vv = 0.f;

#pragma unroll 1
        for (int kk = 0; kk < 9; kk++) {
            int ki = kk / 3, kj = kk - 3 * ki;
            const float* pbase = shp + ki * HALO_W + kj;
#pragma unroll
            for (int kt = 0; kt < 3; kt++) {
                const float* p = pbase + kt * (NC * SH_PLANE);
                float xcol[NC];
#pragma unroll
                for (int c = 0; c < NC; c++) xcol[c] = p[c * SH_PLANE];

                float num = 0.f;
#pragma unroll
                for (int c = 0; c < NC; c++) num = fmaf(u[c], xcol[c], num);

                const int svi = (kk * 3 + kt) * NTHREADS + tid;
                float vk = sv[svi];
                float vn = vk * num * __frcp_rn(fmaf(t_uu, vk, EPSV));
                sv[svi] = vn;
                vv = fmaf(vn, vn, vv);
#pragma unroll
                for (int c = 0; c < NC; c++) nu[c] = fmaf(xcol[c], vn, nu[c]);
            }
        }
        const float t_vv = 3.f * vv;
#pragma unroll
        for (int c = 0; c < NC; c++)
            u[c] = u[c] * nu[c] * __frcp_rn(fmaf(t_vv, u[c], EPSV));
    }

    // ---- center tap + tail GEMV + relu ----
    const float v13 = sv[13 * NTHREADS + tid];
    float uvc[NC];
#pragma unroll
    for (int c = 0; c < NC; c++) uvc[c] = 3.f * u[c] * v13;

    const size_t outbase = (size_t)b * NC * DHW + (size_t)d * HW
                         + (size_t)(y0 + ty) * W_DIM + (x0 + tx);
#pragma unroll
    for (int i = 0; i < NC; i++) {
        float a = 0.f;
#pragma unroll
        for (int o = 0; o < NC; o++) a = fmaf(st[i * NC + o], uvc[o], a);
        out[outbase + (size_t)i * DHW] = fmaxf(a, 0.f);
    }
}

// ---------------------------------------------------------------------------
extern "C" void kernel_launch(void* const* d_in, const int* in_sizes, int n_in,
                              void* d_out, int out_size) {
    const float* x      = (const float*)d_in[0];
    const float* head_w = (const float*)d_in[1];
    const float* tail_w = (const float*)d_in[2];
    float* out = (float*)d_out;

    (void)in_sizes; (void)n_in; (void)out_size;

    cudaFuncSetAttribute(nmf_kernel,
                         cudaFuncAttributeMaxDynamicSharedMemorySize,
                         SMEM_BYTES);

    {   // head: one thread per spatial location
        int total = B_DIM * DHW;
        int threads = 256;
        int blocks = (total + threads - 1) / threads;
        head_kernel<<<blocks, threads>>>(x, head_w);
    }
    {
        dim3 grid(W_DIM / TW, H_DIM / TH, B_DIM * D_DIM);   // (3, 12, 16)
        nmf_kernel<<<grid, NTHREADS, SMEM_BYTES>>>(tail_w, out);
    }
}